// round 2
// baseline (speedup 1.0000x reference)
#include <cuda_runtime.h>
#include <cuda_bf16.h>

#define PROPOSALS_PER_IM 300
#define HUBER_T 3.0f

__global__ void _rpn_zero_kernel(float* out) {
    if (threadIdx.x == 0) out[0] = 0.0f;
}

__device__ __forceinline__ float huber1(float d) {
    float a = fabsf(d);
    return (a < HUBER_T) ? d * d : a;
}

__global__ void _RPN_71459665871443_kernel(const float* __restrict__ out8,
                                           const float* __restrict__ gt,
                                           const int* __restrict__ cp,
                                           float* __restrict__ d_out,
                                           int B, float inv_n) {
    int b = blockIdx.x * blockDim.x + threadIdx.x;
    float s = 0.0f;
    if (b < B) {
        // idx fits in 32 bits (max ~19.7M), byte offset idx*32+16 fits in
        // 64-bit pointer arithmetic via long long promotion below.
        long long idx = (long long)cp[b] + (long long)PROPOSALS_PER_IM * b;
        // row stride 8 floats; pred_box = cols [4..8) -> offset idx*8+4 floats
        // = idx*32+16 bytes, 16B-aligned -> float4 safe.
        float4 p = *reinterpret_cast<const float4*>(out8 + idx * 8 + 4);
        float4 g = *reinterpret_cast<const float4*>(gt + 4LL * b);
        s = huber1(p.x - g.x) + huber1(p.y - g.y) +
            huber1(p.z - g.z) + huber1(p.w - g.w);
    }

    // warp reduction
    #pragma unroll
    for (int off = 16; off > 0; off >>= 1)
        s += __shfl_down_sync(0xFFFFFFFFu, s, off);

    // block reduction across warps
    __shared__ float warp_sums[8];  // 256 threads / 32 warps
    int lane = threadIdx.x & 31;
    int wid  = threadIdx.x >> 5;
    if (lane == 0) warp_sums[wid] = s;
    __syncthreads();
    if (wid == 0) {
        s = (lane < (blockDim.x >> 5)) ? warp_sums[lane] : 0.0f;
        #pragma unroll
        for (int off = 4; off > 0; off >>= 1)
            s += __shfl_down_sync(0xFFFFFFFFu, s, off);
        if (lane == 0)
            atomicAdd(d_out, s * inv_n);
    }
}

extern "C" void kernel_launch(void* const* d_in, const int* in_sizes, int n_in,
                              void* d_out, int out_size) {
    // Identify inputs by element count (order-proof):
    //   output:      B*300*8  (largest)
    //   gt_boxes:    B*4
    //   central_pos: B        (smallest)
    int i_out = 0, i_cp = 0;
    for (int i = 1; i < n_in; i++) {
        if (in_sizes[i] > in_sizes[i_out]) i_out = i;
        if (in_sizes[i] < in_sizes[i_cp])  i_cp  = i;
    }
    int i_gt = 0;
    for (int i = 0; i < n_in; i++)
        if (i != i_out && i != i_cp) { i_gt = i; break; }

    const float* out8 = (const float*)d_in[i_out];
    const float* gt   = (const float*)d_in[i_gt];
    const int*   cp   = (const int*)d_in[i_cp];
    float* out = (float*)d_out;

    int B = in_sizes[i_cp];
    float inv_n = 1.0f / (4.0f * (float)B);

    _rpn_zero_kernel<<<1, 32>>>(out);
    int threads = 256;
    int blocks = (B + threads - 1) / threads;
    _RPN_71459665871443_kernel<<<blocks, threads>>>(out8, gt, cp, out, B, inv_n);
}